// round 10
// baseline (speedup 1.0000x reference)
#include <cuda_runtime.h>
#include <math.h>

// Problem constants
#define NLAT 361
#define NLON 720
#define MMAX 361            // NLON/2 + 1
#define LMAX 360            // NLAT - 1
#define BC   128            // batch*chan
#define NROWS (BC * NLAT)   // 46208 = 361 * 128

#define X_ELEMS  (BC * NLAT * NLON)         // 33,269,760
#define W_ELEMS  (MMAX * LMAX * NLAT)       // 46,915,560
#define OUT_REAL (BC * LMAX * MMAX)         // 16,634,880 float32 (real part)

#define K1P 368             // latitude dim padded (stage-2 K)
#define K2  181             // double-folded DFT length
#define K2P 192             // padded
#define NT1 (K2P / 16)      // 12 k-chunks stage 1
#define NT2 (K1P / 16)      // 23 k-chunks stage 2

// -------- static device scratch (zero-initialized at load) --------
__device__ float sht_te[K2P * K2P];                // even-m trig [k'][j], pad 0
__device__ float sht_to[K2P * K2P];                // odd-m trig  [k'][j], pad 0
__device__ float sht_ye[(size_t)NROWS * K2P];      // even-fold input [r][192]
__device__ float sht_yo[(size_t)NROWS * K2P];      // odd-fold  input [r][192]
__device__ float sht_xfr[(size_t)MMAX * BC * K1P]; // [m][bc][368] real spectra

// ---------------------------------------------------------------
// Trig tables: te[k'][j] = cos(2pi*k'*(2j)/720)*scale  (m = 2j)
//              to[k'][j] = cos(2pi*k'*(2j+1)/720)*scale (m = 2j+1)
// valid k' in [0,180], j in [0,180] (even) / [0,179] (odd); pad = 0.
// ---------------------------------------------------------------
__global__ void sht_init_trig() {
    int idx = blockIdx.x * blockDim.x + threadIdx.x;
    if (idx >= K2P * K2P) return;
    int k = idx / K2P;
    int j = idx - k * K2P;
    const double scale = 6.283185307179586476925286766559 / (double)NLON;
    float ve = 0.f, vo = 0.f;
    if (k <= 180) {
        if (j <= 180) {
            int r = (k * (2 * j)) % NLON;
            ve = (float)(cos(6.283185307179586476925286766559 * (double)r / (double)NLON) * scale);
        }
        if (j <= 179) {
            int r = (k * (2 * j + 1)) % NLON;
            vo = (float)(cos(6.283185307179586476925286766559 * (double)r / (double)NLON) * scale);
        }
    }
    sht_te[idx] = ve;
    sht_to[idx] = vo;
}

// ---------------------------------------------------------------
// Double fold: for n in [0,180]
//   n=0:        ye = x[0]+x[360],                 yo = x[0]-x[360]
//   1<=n<=179:  s1 = x[n]+x[720-n], s2 = x[360-n]+x[360+n]
//               ye = s1+s2,                       yo = s1-s2
//   n=180:      ye = yo = x[180]+x[540]
//   n>180: 0
// ---------------------------------------------------------------
__global__ void sht_fold(const float* __restrict__ x, unsigned xbud) {
    int idx = blockIdx.x * blockDim.x + threadIdx.x;
    if (idx >= NROWS * K2P) return;
    int r = idx / K2P;
    int n = idx - r * K2P;
    float ve = 0.f, vo = 0.f;
    unsigned b = (unsigned)r * NLON;
#define XLD(o) ((b + (unsigned)(o) < xbud) ? x[b + (unsigned)(o)] : 0.f)
    if (n == 0) {
        float a0 = XLD(0), a1 = XLD(360);
        ve = a0 + a1; vo = a0 - a1;
    } else if (n <= 179) {
        float s1 = XLD(n) + XLD(NLON - n);
        float s2 = XLD(360 - n) + XLD(360 + n);
        ve = s1 + s2; vo = s1 - s2;
    } else if (n == 180) {
        float s = XLD(180) + XLD(540);
        ve = s; vo = s;
    }
#undef XLD
    sht_ye[idx] = ve;
    sht_yo[idx] = vo;
}

// ---------------------------------------------------------------
// Stage 1: xf[m][r] = sum_{k'=0}^{180} y_p[r][k'] * trig_p[k'][j]
//          m = 2j+p.  128x128 tile, BK=16 double-buffered,
//          8x8 split microtile. grid=(361, 4): p=by>>1, j0=(by&1)*64.
// ---------------------------------------------------------------
__global__ __launch_bounds__(256, 2) void sht_stage1(int dummy) {
    __shared__ __align__(16) float As[2][16][132];   // [buf][k][row]
    __shared__ __align__(16) float Bs[2][16][132];   // [buf][k][j]

    const int tid  = threadIdx.x;
    const int row0 = blockIdx.x * 128;
    const int p    = blockIdx.y >> 1;
    const int j0   = (blockIdx.y & 1) * 64;
    const int tx   = tid & 15;
    const int ty   = tid >> 4;

    const float* __restrict__ ya = p ? sht_yo : sht_ye;
    const float* __restrict__ tb = p ? sht_to : sht_te;

    float acc[8][8];
#pragma unroll
    for (int j = 0; j < 8; j++)
#pragma unroll
        for (int i = 0; i < 8; i++) acc[j][i] = 0.f;

    const int a_row = tid >> 2;        // 0..63
    const int a_kq  = (tid & 3) * 4;   // 0,4,8,12

#define S1_LOAD(buf, kb) do {                                                   \
        float4 v0 = *(const float4*)&ya[(size_t)(row0 + a_row) * K2P + (kb) + a_kq];      \
        float4 v1 = *(const float4*)&ya[(size_t)(row0 + a_row + 64) * K2P + (kb) + a_kq]; \
        As[buf][a_kq + 0][a_row] = v0.x; As[buf][a_kq + 1][a_row] = v0.y;       \
        As[buf][a_kq + 2][a_row] = v0.z; As[buf][a_kq + 3][a_row] = v0.w;       \
        As[buf][a_kq + 0][a_row + 64] = v1.x; As[buf][a_kq + 1][a_row + 64] = v1.y; \
        As[buf][a_kq + 2][a_row + 64] = v1.z; As[buf][a_kq + 3][a_row + 64] = v1.w; \
        _Pragma("unroll")                                                       \
        for (int i = 0; i < 8; i++) {                                           \
            int f = tid + i * 256;                                              \
            int r = f >> 7;                                                     \
            int c = f & 127;                                                    \
            Bs[buf][r][c] = tb[((kb) + r) * K2P + j0 + c];                      \
        }                                                                       \
    } while (0)

    S1_LOAD(0, 0);
    __syncthreads();

    for (int t = 0; t < NT1; t++) {
        if (t + 1 < NT1) S1_LOAD((t + 1) & 1, 16 * (t + 1));
        const int cb = t & 1;
#pragma unroll
        for (int kk = 0; kk < 16; kk++) {
            float4 a0 = *(const float4*)&As[cb][kk][ty * 4];
            float4 a1 = *(const float4*)&As[cb][kk][ty * 4 + 64];
            float4 b0 = *(const float4*)&Bs[cb][kk][tx * 4];
            float4 b1 = *(const float4*)&Bs[cb][kk][tx * 4 + 64];
            float a[8] = {a0.x, a0.y, a0.z, a0.w, a1.x, a1.y, a1.z, a1.w};
            float b[8] = {b0.x, b0.y, b0.z, b0.w, b1.x, b1.y, b1.z, b1.w};
#pragma unroll
            for (int j = 0; j < 8; j++)
#pragma unroll
                for (int i = 0; i < 8; i++)
                    acc[j][i] = fmaf(a[i], b[j], acc[j][i]);
        }
        __syncthreads();
    }
#undef S1_LOAD

    // Store xfr[m][bc][368]: m = 2*(j0+jj)+p, r -> (bc, k_lat)
#pragma unroll
    for (int j = 0; j < 8; j++) {
        int jj = tx * 4 + (j & 3) + ((j >> 2) << 6);
        int m  = 2 * (j0 + jj) + p;
        if (m > 360) continue;
        size_t mb = (size_t)m * BC * K1P;
#pragma unroll
        for (int i = 0; i < 8; i++) {
            int r  = row0 + ty * 4 + (i & 3) + ((i >> 2) << 6);
            int bc = r / NLAT;
            int k  = r - bc * NLAT;
            sht_xfr[mb + (size_t)bc * K1P + k] = acc[j][i];
        }
    }
}

// ---------------------------------------------------------------
// Stage 2: out[(bc*360+l)*361+m] = sum_k xfr[m][bc][k] * w[m][l][k]
// 128(bc)x128(l) tile, BK=16 double-buffered, 8x8 split microtile.
// grid=(3, 361)
// ---------------------------------------------------------------
__global__ __launch_bounds__(256, 2) void sht_stage2(const float* __restrict__ w,
                                                     float* __restrict__ out,
                                                     unsigned wbud, unsigned obud) {
    __shared__ __align__(16) float As[2][16][132];   // [buf][k][bc]
    __shared__ __align__(16) float Ws[2][16][132];   // [buf][k][l]

    const int tid = threadIdx.x;
    const int m   = blockIdx.y;
    const int l0  = blockIdx.x * 128;
    const int tx  = tid & 15;
    const int ty  = tid >> 4;

    const float* __restrict__ xa = sht_xfr + (size_t)m * BC * K1P;

    float acc[8][8];
#pragma unroll
    for (int j = 0; j < 8; j++)
#pragma unroll
        for (int i = 0; i < 8; i++) acc[j][i] = 0.f;

    const int a_bc = tid >> 2;
    const int a_kq = (tid & 3) * 4;

#define S2_LOAD(buf, kb) do {                                                   \
        float4 v0 = *(const float4*)&xa[(size_t)a_bc * K1P + (kb) + a_kq];      \
        float4 v1 = *(const float4*)&xa[(size_t)(a_bc + 64) * K1P + (kb) + a_kq]; \
        As[buf][a_kq + 0][a_bc] = v0.x; As[buf][a_kq + 1][a_bc] = v0.y;         \
        As[buf][a_kq + 2][a_bc] = v0.z; As[buf][a_kq + 3][a_bc] = v0.w;         \
        As[buf][a_kq + 0][a_bc + 64] = v1.x; As[buf][a_kq + 1][a_bc + 64] = v1.y; \
        As[buf][a_kq + 2][a_bc + 64] = v1.z; As[buf][a_kq + 3][a_bc + 64] = v1.w; \
        _Pragma("unroll")                                                       \
        for (int i = 0; i < 8; i++) {                                           \
            int f  = tid + i * 256;                                             \
            int kk = f & 15;                                                    \
            int l  = f >> 4;                                                    \
            int k  = (kb) + kk;                                                 \
            int ll = l0 + l;                                                    \
            float v = 0.f;                                                      \
            if (k < NLAT && ll < LMAX) {                                        \
                unsigned gi = (unsigned)m * (LMAX * NLAT) + (unsigned)ll * NLAT + (unsigned)k; \
                if (gi < wbud) v = w[gi];                                       \
            }                                                                   \
            Ws[buf][kk][l] = v;                                                 \
        }                                                                       \
    } while (0)

    S2_LOAD(0, 0);
    __syncthreads();

    for (int t = 0; t < NT2; t++) {
        if (t + 1 < NT2) S2_LOAD((t + 1) & 1, 16 * (t + 1));
        const int cb = t & 1;
#pragma unroll
        for (int kk = 0; kk < 16; kk++) {
            float4 a0 = *(const float4*)&As[cb][kk][ty * 4];
            float4 a1 = *(const float4*)&As[cb][kk][ty * 4 + 64];
            float4 w0 = *(const float4*)&Ws[cb][kk][tx * 4];
            float4 w1 = *(const float4*)&Ws[cb][kk][tx * 4 + 64];
            float a[8] = {a0.x, a0.y, a0.z, a0.w, a1.x, a1.y, a1.z, a1.w};
            float b[8] = {w0.x, w0.y, w0.z, w0.w, w1.x, w1.y, w1.z, w1.w};
#pragma unroll
            for (int j = 0; j < 8; j++)
#pragma unroll
                for (int i = 0; i < 8; i++)
                    acc[j][i] = fmaf(a[i], b[j], acc[j][i]);
        }
        __syncthreads();
    }
#undef S2_LOAD

    // Store real part: out[(bc*360 + l)*361 + m]
#pragma unroll
    for (int j = 0; j < 8; j++) {
        int l = l0 + tx * 4 + (j & 3) + ((j >> 2) << 6);
        if (l >= LMAX) continue;
#pragma unroll
        for (int i = 0; i < 8; i++) {
            int bc = ty * 4 + (i & 3) + ((i >> 2) << 6);
            unsigned ci = ((unsigned)bc * LMAX + (unsigned)l) * MMAX + (unsigned)m;
            if (ci < obud) out[ci] = acc[j][i];
        }
    }
}

// ---------------------------------------------------------------
extern "C" void kernel_launch(void* const* d_in, const int* in_sizes, int n_in,
                              void* d_out, int out_size) {
    const float* x = nullptr;
    const float* w = nullptr;
    unsigned xbud = 0, wbud = 0;

    for (int i = 0; i < n_in; i++) {
        if (in_sizes[i] == X_ELEMS && !x) { x = (const float*)d_in[i]; xbud = X_ELEMS; }
        else if (in_sizes[i] == W_ELEMS && !w) { w = (const float*)d_in[i]; wbud = W_ELEMS; }
    }
    if (!x && n_in >= 1) {
        x = (const float*)d_in[0];
        long s = in_sizes[0];
        xbud = (unsigned)((s > 0 && s < (long)X_ELEMS) ? s : X_ELEMS);
    }
    if (!w && n_in >= 2) {
        w = (const float*)d_in[1];
        long s = in_sizes[1];
        wbud = (unsigned)((s > 0 && s < (long)W_ELEMS) ? s : W_ELEMS);
    }

    unsigned obud;
    if (out_size <= 0) obud = OUT_REAL;
    else obud = ((unsigned)out_size < (unsigned)OUT_REAL) ? (unsigned)out_size
                                                          : (unsigned)OUT_REAL;

    float* out = (float*)d_out;

    sht_init_trig<<<(K2P * K2P + 255) / 256, 256>>>();
    sht_fold<<<(NROWS * K2P + 255) / 256, 256>>>(x, xbud);
    sht_stage1<<<dim3(361, 4), 256>>>(0);
    sht_stage2<<<dim3(3, MMAX), 256>>>(w, out, wbud, obud);
}

// round 11
// speedup vs baseline: 1.0755x; 1.0755x over previous
#include <cuda_runtime.h>
#include <math.h>
#include <stdint.h>

// Problem constants
#define NLAT 361
#define NLON 720
#define MMAX 361
#define LMAX 360
#define BC   128
#define NROWS (BC * NLAT)   // 46208

#define X_ELEMS  (BC * NLAT * NLON)
#define W_ELEMS  (MMAX * LMAX * NLAT)
#define OUT_REAL (BC * LMAX * MMAX)

#define K1P 368             // latitude K padded (stage-2)
#define K2P 192             // folded DFT K padded (stage-1)
#define NT1 (K2P / 16)      // 12
#define NT2 (K1P / 16)      // 23
#define LPAD 384            // stage-2 out scratch l-pad

// -------- static device scratch (zero-initialized at load) --------
__device__ float sht_te[K2P * K2P];                 // [k][j] even-m trig
__device__ float sht_to[K2P * K2P];                 // [k][j] odd-m trig
__device__ float sht_ye[(size_t)K2P * NROWS];       // [k][r] even fold
__device__ float sht_yo[(size_t)K2P * NROWS];       // [k][r] odd fold
__device__ float sht_xfr1[(size_t)MMAX * BC * K1P]; // [m][bc][k]
__device__ float sht_xfr2[(size_t)MMAX * K1P * BC]; // [m][k][bc]
__device__ float sht_s2[(size_t)MMAX * BC * LPAD];  // [m][bc][l]

// -------- cp.async helpers --------
#define CP_ASYNC16(s, g) asm volatile("cp.async.ca.shared.global [%0], [%1], 16;" :: "r"(s), "l"(g) : "memory")
#define CP_ASYNC4(s, g)  asm volatile("cp.async.ca.shared.global [%0], [%1], 4;"  :: "r"(s), "l"(g) : "memory")
#define CP_COMMIT()      asm volatile("cp.async.commit_group;" ::: "memory")
#define CP_WAIT1()       asm volatile("cp.async.wait_group 1;" ::: "memory")
#define CP_WAIT0()       asm volatile("cp.async.wait_group 0;" ::: "memory")

// ---------------------------------------------------------------
__global__ void sht_init_trig() {
    int idx = blockIdx.x * blockDim.x + threadIdx.x;
    if (idx >= K2P * K2P) return;
    int k = idx / K2P;
    int j = idx - k * K2P;
    const double scale = 6.283185307179586476925286766559 / (double)NLON;
    float ve = 0.f, vo = 0.f;
    if (k <= 180) {
        if (j <= 180) {
            int r = (k * (2 * j)) % NLON;
            ve = (float)(cos(6.283185307179586476925286766559 * (double)r / (double)NLON) * scale);
        }
        if (j <= 179) {
            int r = (k * (2 * j + 1)) % NLON;
            vo = (float)(cos(6.283185307179586476925286766559 * (double)r / (double)NLON) * scale);
        }
    }
    sht_te[idx] = ve;
    sht_to[idx] = vo;
}

// ---------------------------------------------------------------
// Fold to k-major: ye/yo[n][r].  16 rows per block via smem.
// ---------------------------------------------------------------
__global__ __launch_bounds__(256) void sht_fold(const float* __restrict__ x,
                                                unsigned xbud) {
    __shared__ float xs[16][720];
    const int row0 = blockIdx.x * 16;
    const int tid  = threadIdx.x;

    for (int i = tid; i < 16 * 720; i += 256) {
        int rl = i / 720, n = i - (i / 720) * 720;
        unsigned gi = (unsigned)(row0 + rl) * NLON + (unsigned)n;
        xs[rl][n] = (gi < xbud) ? x[gi] : 0.f;
    }
    __syncthreads();

    const int rl = tid & 15;
#pragma unroll
    for (int it = 0; it < 12; it++) {
        int n = (tid >> 4) + 16 * it;   // 0..191
        float ve = 0.f, vo = 0.f;
        if (n == 0) {
            float a0 = xs[rl][0], a1 = xs[rl][360];
            ve = a0 + a1; vo = a0 - a1;
        } else if (n <= 179) {
            float s1 = xs[rl][n] + xs[rl][720 - n];
            float s2 = xs[rl][360 - n] + xs[rl][360 + n];
            ve = s1 + s2; vo = s1 - s2;
        } else if (n == 180) {
            float s = xs[rl][180] + xs[rl][540];
            ve = s; vo = s;
        }
        size_t o = (size_t)n * NROWS + row0 + rl;
        sht_ye[o] = ve;
        sht_yo[o] = vo;
    }
}

// ---------------------------------------------------------------
// Stage 1: xfr1[m][bc][k_lat] = sum_k y_p[k][r] * trig_p[k][j], m=2j+p
// 128x128 tile, cp.async 2-stage pipeline, 8x8 microtile.
// grid=(361, 4): p = by>>1, j0 = (by&1)*64.
// ---------------------------------------------------------------
__global__ __launch_bounds__(256, 2) void sht_stage1() {
    __shared__ __align__(16) float As[2][16][128];
    __shared__ __align__(16) float Bs[2][16][128];

    const int tid  = threadIdx.x;
    const int row0 = blockIdx.x * 128;
    const int p    = blockIdx.y >> 1;
    const int j0   = (blockIdx.y & 1) * 64;
    const int tx   = tid & 15;
    const int ty   = tid >> 4;

    const float* __restrict__ ya = p ? sht_yo : sht_ye;
    const float* __restrict__ tb = p ? sht_to : sht_te;

    const uint32_t sAs = (uint32_t)__cvta_generic_to_shared(&As[0][0][0]);
    const uint32_t sBs = (uint32_t)__cvta_generic_to_shared(&Bs[0][0][0]);

    float acc[8][8];
#pragma unroll
    for (int j = 0; j < 8; j++)
#pragma unroll
        for (int i = 0; i < 8; i++) acc[j][i] = 0.f;

#define S1_LOAD(buf, kb) do {                                                  \
        _Pragma("unroll")                                                      \
        for (int i = 0; i < 2; i++) {                                          \
            int f  = tid + i * 256;                                            \
            int kk = f >> 5;                                                   \
            int c4 = (f & 31) * 4;                                             \
            CP_ASYNC16(sAs + (uint32_t)((((buf)*16 + kk)*128 + c4) * 4),       \
                       ya + (size_t)((kb) + kk) * NROWS + row0 + c4);          \
            CP_ASYNC16(sBs + (uint32_t)((((buf)*16 + kk)*128 + c4) * 4),       \
                       tb + ((kb) + kk) * K2P + j0 + c4);                      \
        }                                                                      \
        CP_COMMIT();                                                           \
    } while (0)

    S1_LOAD(0, 0);

    for (int t = 0; t < NT1; t++) {
        if (t + 1 < NT1) { S1_LOAD((t + 1) & 1, 16 * (t + 1)); CP_WAIT1(); }
        else             { CP_WAIT0(); }
        __syncthreads();
        const int cb = t & 1;
#pragma unroll
        for (int kk = 0; kk < 16; kk++) {
            float4 a0 = *(const float4*)&As[cb][kk][ty * 4];
            float4 a1 = *(const float4*)&As[cb][kk][ty * 4 + 64];
            float4 b0 = *(const float4*)&Bs[cb][kk][tx * 4];
            float4 b1 = *(const float4*)&Bs[cb][kk][tx * 4 + 64];
            float a[8] = {a0.x, a0.y, a0.z, a0.w, a1.x, a1.y, a1.z, a1.w};
            float b[8] = {b0.x, b0.y, b0.z, b0.w, b1.x, b1.y, b1.z, b1.w};
#pragma unroll
            for (int j = 0; j < 8; j++)
#pragma unroll
                for (int i = 0; i < 8; i++)
                    acc[j][i] = fmaf(a[i], b[j], acc[j][i]);
        }
        __syncthreads();
    }
#undef S1_LOAD

    // Store xfr1[m][bc][k]
#pragma unroll
    for (int j = 0; j < 8; j++) {
        int jj = tx * 4 + (j & 3) + ((j >> 2) << 6);
        int m  = 2 * (j0 + jj) + p;
        if (m > 360) continue;
        size_t mb = (size_t)m * BC * K1P;
#pragma unroll
        for (int i = 0; i < 8; i++) {
            int r  = row0 + ty * 4 + (i & 3) + ((i >> 2) << 6);
            int bc = r / NLAT;
            int k  = r - bc * NLAT;
            sht_xfr1[mb + (size_t)bc * K1P + k] = acc[j][i];
        }
    }
}

// ---------------------------------------------------------------
// Transpose xfr1[m][bc][k] -> xfr2[m][k][bc].  grid=(12,4,361), block=(32,8)
// ---------------------------------------------------------------
__global__ void sht_xpose_xfr() {
    __shared__ float t[32][33];
    const int m  = blockIdx.z;
    const int k0 = blockIdx.x * 32;
    const int b0 = blockIdx.y * 32;
    const size_t mb1 = (size_t)m * BC * K1P;
    const size_t mb2 = (size_t)m * K1P * BC;

    for (int i = threadIdx.y; i < 32; i += 8) {
        int k = k0 + threadIdx.x;
        t[i][threadIdx.x] = (k < K1P) ? sht_xfr1[mb1 + (size_t)(b0 + i) * K1P + k] : 0.f;
    }
    __syncthreads();
    for (int i = threadIdx.y; i < 32; i += 8) {
        int k = k0 + i;
        if (k < K1P)
            sht_xfr2[mb2 + (size_t)k * BC + b0 + threadIdx.x] = t[threadIdx.x][i];
    }
}

// ---------------------------------------------------------------
// Stage 2: s2[m][bc][l] = sum_k xfr2[m][k][bc] * w[m][l][k]
// 128x128 tile, cp.async 2-stage pipeline, 8x8 microtile. grid=(3,361)
// ---------------------------------------------------------------
__global__ __launch_bounds__(256, 2) void sht_stage2(const float* __restrict__ w,
                                                     unsigned wbud) {
    __shared__ __align__(16) float As[2][16][128];
    __shared__ __align__(16) float Ws[2][16][128];

    const int tid = threadIdx.x;
    const int m   = blockIdx.y;
    const int l0  = blockIdx.x * 128;
    const int tx  = tid & 15;
    const int ty  = tid >> 4;

    const float* __restrict__ xa = sht_xfr2 + (size_t)m * K1P * BC;

    const uint32_t sAs = (uint32_t)__cvta_generic_to_shared(&As[0][0][0]);
    const uint32_t sWs = (uint32_t)__cvta_generic_to_shared(&Ws[0][0][0]);

    float acc[8][8];
#pragma unroll
    for (int j = 0; j < 8; j++)
#pragma unroll
        for (int i = 0; i < 8; i++) acc[j][i] = 0.f;

#define S2_LOAD(buf, kb) do {                                                  \
        _Pragma("unroll")                                                      \
        for (int i = 0; i < 2; i++) {                                          \
            int f  = tid + i * 256;                                            \
            int kk = f >> 5;                                                   \
            int c4 = (f & 31) * 4;                                             \
            CP_ASYNC16(sAs + (uint32_t)((((buf)*16 + kk)*128 + c4) * 4),       \
                       xa + (size_t)((kb) + kk) * BC + c4);                    \
        }                                                                      \
        _Pragma("unroll")                                                      \
        for (int i = 0; i < 8; i++) {                                          \
            int f  = tid + i * 256;                                            \
            int kk = f & 15;                                                   \
            int l  = f >> 4;                                                   \
            int k  = (kb) + kk;                                                \
            int ll = l0 + l;                                                   \
            unsigned gi = (unsigned)m * (LMAX * NLAT) + (unsigned)ll * NLAT + (unsigned)k; \
            if (k < NLAT && ll < LMAX && gi < wbud)                            \
                CP_ASYNC4(sWs + (uint32_t)((((buf)*16 + kk)*128 + l) * 4), w + gi); \
            else Ws[buf][kk][l] = 0.f;                                         \
        }                                                                      \
        CP_COMMIT();                                                           \
    } while (0)

    S2_LOAD(0, 0);

    for (int t = 0; t < NT2; t++) {
        if (t + 1 < NT2) { S2_LOAD((t + 1) & 1, 16 * (t + 1)); CP_WAIT1(); }
        else             { CP_WAIT0(); }
        __syncthreads();
        const int cb = t & 1;
#pragma unroll
        for (int kk = 0; kk < 16; kk++) {
            float4 a0 = *(const float4*)&As[cb][kk][ty * 4];
            float4 a1 = *(const float4*)&As[cb][kk][ty * 4 + 64];
            float4 w0 = *(const float4*)&Ws[cb][kk][tx * 4];
            float4 w1 = *(const float4*)&Ws[cb][kk][tx * 4 + 64];
            float a[8] = {a0.x, a0.y, a0.z, a0.w, a1.x, a1.y, a1.z, a1.w};
            float b[8] = {w0.x, w0.y, w0.z, w0.w, w1.x, w1.y, w1.z, w1.w};
#pragma unroll
            for (int j = 0; j < 8; j++)
#pragma unroll
                for (int i = 0; i < 8; i++)
                    acc[j][i] = fmaf(a[i], b[j], acc[j][i]);
        }
        __syncthreads();
    }
#undef S2_LOAD

    // Coalesced float4 store to s2[m][bc][l]
    const size_t sb = (size_t)m * (BC * LPAD);
#pragma unroll
    for (int i = 0; i < 8; i++) {
        int bc = ty * 4 + (i & 3) + ((i >> 2) << 6);
        float4 v0 = make_float4(acc[0][i], acc[1][i], acc[2][i], acc[3][i]);
        float4 v1 = make_float4(acc[4][i], acc[5][i], acc[6][i], acc[7][i]);
        *(float4*)&sht_s2[sb + (size_t)bc * LPAD + l0 + tx * 4]      = v0;
        *(float4*)&sht_s2[sb + (size_t)bc * LPAD + l0 + tx * 4 + 64] = v1;
    }
}

// ---------------------------------------------------------------
// Output transpose: s2[m][bc][l] -> out[(bc*360+l)*361+m]
// grid=(12 lt, 12 mt, 128 bc), block=(32,8)
// ---------------------------------------------------------------
__global__ void sht_xpose_out(float* __restrict__ out, unsigned obud) {
    __shared__ float t[32][33];
    const int l0 = blockIdx.x * 32;
    const int m0 = blockIdx.y * 32;
    const int bc = blockIdx.z;

    for (int i = threadIdx.y; i < 32; i += 8) {
        int m = m0 + i;
        float v = 0.f;
        if (m < MMAX)
            v = sht_s2[(size_t)m * (BC * LPAD) + (size_t)bc * LPAD + l0 + threadIdx.x];
        t[i][threadIdx.x] = v;
    }
    __syncthreads();
    for (int i = threadIdx.y; i < 32; i += 8) {
        int l = l0 + i;
        int m = m0 + threadIdx.x;
        if (l < LMAX && m < MMAX) {
            unsigned ci = ((unsigned)bc * LMAX + (unsigned)l) * MMAX + (unsigned)m;
            if (ci < obud) out[ci] = t[threadIdx.x][i];
        }
    }
}

// ---------------------------------------------------------------
extern "C" void kernel_launch(void* const* d_in, const int* in_sizes, int n_in,
                              void* d_out, int out_size) {
    const float* x = nullptr;
    const float* w = nullptr;
    unsigned xbud = 0, wbud = 0;

    for (int i = 0; i < n_in; i++) {
        if (in_sizes[i] == X_ELEMS && !x) { x = (const float*)d_in[i]; xbud = X_ELEMS; }
        else if (in_sizes[i] == W_ELEMS && !w) { w = (const float*)d_in[i]; wbud = W_ELEMS; }
    }
    if (!x && n_in >= 1) {
        x = (const float*)d_in[0];
        long s = in_sizes[0];
        xbud = (unsigned)((s > 0 && s < (long)X_ELEMS) ? s : X_ELEMS);
    }
    if (!w && n_in >= 2) {
        w = (const float*)d_in[1];
        long s = in_sizes[1];
        wbud = (unsigned)((s > 0 && s < (long)W_ELEMS) ? s : W_ELEMS);
    }

    unsigned obud;
    if (out_size <= 0) obud = OUT_REAL;
    else obud = ((unsigned)out_size < (unsigned)OUT_REAL) ? (unsigned)out_size
                                                          : (unsigned)OUT_REAL;

    float* out = (float*)d_out;

    sht_init_trig<<<(K2P * K2P + 255) / 256, 256>>>();
    sht_fold<<<NROWS / 16, 256>>>(x, xbud);
    sht_stage1<<<dim3(361, 4), 256>>>();
    sht_xpose_xfr<<<dim3(12, 4, 361), dim3(32, 8)>>>();
    sht_stage2<<<dim3(3, MMAX), 256>>>(w, wbud);
    sht_xpose_out<<<dim3(12, 12, 128), dim3(32, 8)>>>(out, obud);
}

// round 12
// speedup vs baseline: 2.0976x; 1.9502x over previous
#include <cuda_runtime.h>
#include <math.h>
#include <stdint.h>

// Problem constants
#define NLAT 361
#define NLON 720
#define MMAX 361
#define LMAX 360
#define BC   128
#define NROWS (BC * NLAT)   // 46208

#define X_ELEMS  (BC * NLAT * NLON)
#define W_ELEMS  (MMAX * LMAX * NLAT)
#define OUT_REAL (BC * LMAX * MMAX)

#define K1P 368             // latitude K padded (stage-2)
#define K2P 192             // folded DFT K padded (stage-1)
#define NT1 (K2P / 16)      // 12
#define NT2 (K1P / 16)      // 23
#define LPAD 384
#define SPITCH 132          // smem row pitch (bank-shift padding)

// -------- static device scratch (zero-initialized at load) --------
__device__ float sht_te[K2P * K2P];
__device__ float sht_to[K2P * K2P];
__device__ float sht_ye[(size_t)K2P * NROWS];
__device__ float sht_yo[(size_t)K2P * NROWS];
__device__ float sht_xfr1[(size_t)MMAX * BC * K1P]; // [m][bc][k]
__device__ float sht_xfr2[(size_t)MMAX * K1P * BC]; // [m][k][bc] (tf32-rounded)
__device__ float sht_s2[(size_t)MMAX * BC * LPAD];  // [m][bc][l]

#define CP_ASYNC16(s, g) asm volatile("cp.async.ca.shared.global [%0], [%1], 16;" :: "r"(s), "l"(g) : "memory")
#define CP_ASYNC4(s, g)  asm volatile("cp.async.ca.shared.global [%0], [%1], 4;"  :: "r"(s), "l"(g) : "memory")
#define CP_COMMIT()      asm volatile("cp.async.commit_group;" ::: "memory")
#define CP_WAIT1()       asm volatile("cp.async.wait_group 1;" ::: "memory")
#define CP_WAIT0()       asm volatile("cp.async.wait_group 0;" ::: "memory")

__device__ __forceinline__ float tf32_round(float x) {
    uint32_t u;
    asm("cvt.rna.tf32.f32 %0, %1;" : "=r"(u) : "f"(x));
    return __uint_as_float(u);
}
__device__ __forceinline__ uint32_t tf32_bits(float x) {
    uint32_t u;
    asm("cvt.rna.tf32.f32 %0, %1;" : "=r"(u) : "f"(x));
    return u;
}
#define MMA_TF32(d, a, b) \
    asm volatile("mma.sync.aligned.m16n8k8.row.col.f32.tf32.tf32.f32 " \
        "{%0,%1,%2,%3}, {%4,%5,%6,%7}, {%8,%9}, {%0,%1,%2,%3};" \
        : "+f"((d)[0]), "+f"((d)[1]), "+f"((d)[2]), "+f"((d)[3]) \
        : "r"((a)[0]), "r"((a)[1]), "r"((a)[2]), "r"((a)[3]), "r"((b)[0]), "r"((b)[1]))

// ---------------------------------------------------------------
__global__ void sht_init_trig() {
    int idx = blockIdx.x * blockDim.x + threadIdx.x;
    if (idx >= K2P * K2P) return;
    int k = idx / K2P;
    int j = idx - k * K2P;
    const double scale = 6.283185307179586476925286766559 / (double)NLON;
    float ve = 0.f, vo = 0.f;
    if (k <= 180) {
        if (j <= 180) {
            int r = (k * (2 * j)) % NLON;
            ve = (float)(cos(6.283185307179586476925286766559 * (double)r / (double)NLON) * scale);
        }
        if (j <= 179) {
            int r = (k * (2 * j + 1)) % NLON;
            vo = (float)(cos(6.283185307179586476925286766559 * (double)r / (double)NLON) * scale);
        }
    }
    sht_te[idx] = tf32_round(ve);
    sht_to[idx] = tf32_round(vo);
}

// ---------------------------------------------------------------
__global__ __launch_bounds__(256) void sht_fold(const float* __restrict__ x,
                                                unsigned xbud) {
    __shared__ float xs[16][720];
    const int row0 = blockIdx.x * 16;
    const int tid  = threadIdx.x;

    for (int i = tid; i < 16 * 720; i += 256) {
        int rl = i / 720, n = i - (i / 720) * 720;
        unsigned gi = (unsigned)(row0 + rl) * NLON + (unsigned)n;
        xs[rl][n] = (gi < xbud) ? x[gi] : 0.f;
    }
    __syncthreads();

    const int rl = tid & 15;
#pragma unroll
    for (int it = 0; it < 12; it++) {
        int n = (tid >> 4) + 16 * it;
        float ve = 0.f, vo = 0.f;
        if (n == 0) {
            float a0 = xs[rl][0], a1 = xs[rl][360];
            ve = a0 + a1; vo = a0 - a1;
        } else if (n <= 179) {
            float s1 = xs[rl][n] + xs[rl][720 - n];
            float s2 = xs[rl][360 - n] + xs[rl][360 + n];
            ve = s1 + s2; vo = s1 - s2;
        } else if (n == 180) {
            float s = xs[rl][180] + xs[rl][540];
            ve = s; vo = s;
        }
        size_t o = (size_t)n * NROWS + row0 + rl;
        sht_ye[o] = tf32_round(ve);
        sht_yo[o] = tf32_round(vo);
    }
}

// ---------------------------------------------------------------
// Stage 1 (tensor): per block 128 r-rows x 128 j-cols, K=192.
// grid=(361,4): p=by>>1, j0=(by&1)*64.  mma.m16n8k8.tf32.
// ---------------------------------------------------------------
__global__ __launch_bounds__(256, 2) void sht_stage1() {
    __shared__ __align__(16) float As[2][16][SPITCH];
    __shared__ __align__(16) float Bs[2][16][SPITCH];

    const int tid  = threadIdx.x;
    const int row0 = blockIdx.x * 128;
    const int p    = blockIdx.y >> 1;
    const int j0   = (blockIdx.y & 1) * 64;
    const int wid  = tid >> 5;
    const int lane = tid & 31;
    const int wm   = wid & 3;      // row group (32 rows)
    const int wn   = wid >> 2;     // col group (64 cols)
    const int lr   = lane >> 2;
    const int lk   = lane & 3;

    const float* __restrict__ ya = p ? sht_yo : sht_ye;
    const float* __restrict__ tb = p ? sht_to : sht_te;

    const uint32_t sAs = (uint32_t)__cvta_generic_to_shared(&As[0][0][0]);
    const uint32_t sBs = (uint32_t)__cvta_generic_to_shared(&Bs[0][0][0]);

    float d[2][8][4];
#pragma unroll
    for (int g = 0; g < 2; g++)
#pragma unroll
        for (int n = 0; n < 8; n++)
#pragma unroll
            for (int i = 0; i < 4; i++) d[g][n][i] = 0.f;

#define S1_LOAD(buf, kb) do {                                                  \
        _Pragma("unroll")                                                      \
        for (int i = 0; i < 2; i++) {                                          \
            int f  = tid + i * 256;                                            \
            int kk = f >> 5;                                                   \
            int c4 = (f & 31) * 4;                                             \
            CP_ASYNC16(sAs + (uint32_t)((((buf)*16 + kk)*SPITCH + c4) * 4),    \
                       ya + (size_t)((kb) + kk) * NROWS + row0 + c4);          \
            CP_ASYNC16(sBs + (uint32_t)((((buf)*16 + kk)*SPITCH + c4) * 4),    \
                       tb + ((kb) + kk) * K2P + j0 + c4);                      \
        }                                                                      \
        CP_COMMIT();                                                           \
    } while (0)

    S1_LOAD(0, 0);

    for (int t = 0; t < NT1; t++) {
        if (t + 1 < NT1) { S1_LOAD((t + 1) & 1, 16 * (t + 1)); CP_WAIT1(); }
        else             { CP_WAIT0(); }
        __syncthreads();
        const int cb = t & 1;
#pragma unroll
        for (int kc = 0; kc < 16; kc += 8) {
            uint32_t a[2][4];
#pragma unroll
            for (int g = 0; g < 2; g++) {
                int rb = wm * 32 + g * 16 + lr;
                a[g][0] = __float_as_uint(As[cb][kc + lk][rb]);
                a[g][1] = __float_as_uint(As[cb][kc + lk][rb + 8]);
                a[g][2] = __float_as_uint(As[cb][kc + 4 + lk][rb]);
                a[g][3] = __float_as_uint(As[cb][kc + 4 + lk][rb + 8]);
            }
#pragma unroll
            for (int n = 0; n < 8; n++) {
                int cc = wn * 64 + n * 8 + lr;
                uint32_t b[2];
                b[0] = __float_as_uint(Bs[cb][kc + lk][cc]);
                b[1] = __float_as_uint(Bs[cb][kc + 4 + lk][cc]);
#pragma unroll
                for (int g = 0; g < 2; g++) MMA_TF32(d[g][n], a[g], b);
            }
        }
        __syncthreads();
    }
#undef S1_LOAD

    // Store xfr1[m][bc][k]; m = 2*(j0+jj)+p
#pragma unroll
    for (int g = 0; g < 2; g++) {
#pragma unroll
        for (int n = 0; n < 8; n++) {
#pragma unroll
            for (int e = 0; e < 4; e++) {
                int r  = row0 + wm * 32 + g * 16 + lr + ((e >> 1) << 3);
                int jj = wn * 64 + n * 8 + 2 * lk + (e & 1);
                int m  = 2 * (j0 + jj) + p;
                if (m > 360) continue;
                int bc = r / NLAT;
                int k  = r - bc * NLAT;
                sht_xfr1[(size_t)m * BC * K1P + (size_t)bc * K1P + k] = d[g][n][e];
            }
        }
    }
}

// ---------------------------------------------------------------
// Transpose xfr1[m][bc][k] -> xfr2[m][k][bc] with tf32 rounding.
// ---------------------------------------------------------------
__global__ void sht_xpose_xfr() {
    __shared__ float t[32][33];
    const int m  = blockIdx.z;
    const int k0 = blockIdx.x * 32;
    const int b0 = blockIdx.y * 32;
    const size_t mb1 = (size_t)m * BC * K1P;
    const size_t mb2 = (size_t)m * K1P * BC;

    for (int i = threadIdx.y; i < 32; i += 8) {
        int k = k0 + threadIdx.x;
        t[i][threadIdx.x] = (k < K1P) ? sht_xfr1[mb1 + (size_t)(b0 + i) * K1P + k] : 0.f;
    }
    __syncthreads();
    for (int i = threadIdx.y; i < 32; i += 8) {
        int k = k0 + i;
        if (k < K1P)
            sht_xfr2[mb2 + (size_t)k * BC + b0 + threadIdx.x] =
                tf32_round(t[threadIdx.x][i]);
    }
}

// ---------------------------------------------------------------
// Stage 2 (tensor): s2[m][bc][l] = sum_k xfr2[m][k][bc] * w[m][l][k]
// 128(bc) x 128(l), K=368.  grid=(3,361).
// ---------------------------------------------------------------
__global__ __launch_bounds__(256, 2) void sht_stage2(const float* __restrict__ w,
                                                     unsigned wbud) {
    __shared__ __align__(16) float As[2][16][SPITCH];
    __shared__ __align__(16) float Ws[2][16][SPITCH];

    const int tid = threadIdx.x;
    const int m   = blockIdx.y;
    const int l0  = blockIdx.x * 128;
    const int wid  = tid >> 5;
    const int lane = tid & 31;
    const int wm   = wid & 3;
    const int wn   = wid >> 2;
    const int lr   = lane >> 2;
    const int lk   = lane & 3;

    const float* __restrict__ xa = sht_xfr2 + (size_t)m * K1P * BC;

    const uint32_t sAs = (uint32_t)__cvta_generic_to_shared(&As[0][0][0]);
    const uint32_t sWs = (uint32_t)__cvta_generic_to_shared(&Ws[0][0][0]);

    float d[2][8][4];
#pragma unroll
    for (int g = 0; g < 2; g++)
#pragma unroll
        for (int n = 0; n < 8; n++)
#pragma unroll
            for (int i = 0; i < 4; i++) d[g][n][i] = 0.f;

#define S2_LOAD(buf, kb) do {                                                  \
        _Pragma("unroll")                                                      \
        for (int i = 0; i < 2; i++) {                                          \
            int f  = tid + i * 256;                                            \
            int kk = f >> 5;                                                   \
            int c4 = (f & 31) * 4;                                             \
            CP_ASYNC16(sAs + (uint32_t)((((buf)*16 + kk)*SPITCH + c4) * 4),    \
                       xa + (size_t)((kb) + kk) * BC + c4);                    \
        }                                                                      \
        _Pragma("unroll")                                                      \
        for (int i = 0; i < 8; i++) {                                          \
            int f  = tid + i * 256;                                            \
            int kk = f & 15;                                                   \
            int l  = f >> 4;                                                   \
            int k  = (kb) + kk;                                                \
            int ll = l0 + l;                                                   \
            unsigned gi = (unsigned)m * (LMAX * NLAT) + (unsigned)ll * NLAT + (unsigned)k; \
            if (k < NLAT && ll < LMAX && gi < wbud)                            \
                CP_ASYNC4(sWs + (uint32_t)((((buf)*16 + kk)*SPITCH + l) * 4), w + gi); \
            else Ws[buf][kk][l] = 0.f;                                         \
        }                                                                      \
        CP_COMMIT();                                                           \
    } while (0)

    S2_LOAD(0, 0);

    for (int t = 0; t < NT2; t++) {
        if (t + 1 < NT2) { S2_LOAD((t + 1) & 1, 16 * (t + 1)); CP_WAIT1(); }
        else             { CP_WAIT0(); }
        __syncthreads();
        const int cb = t & 1;
#pragma unroll
        for (int kc = 0; kc < 16; kc += 8) {
            uint32_t a[2][4];
#pragma unroll
            for (int g = 0; g < 2; g++) {
                int rb = wm * 32 + g * 16 + lr;
                a[g][0] = __float_as_uint(As[cb][kc + lk][rb]);
                a[g][1] = __float_as_uint(As[cb][kc + lk][rb + 8]);
                a[g][2] = __float_as_uint(As[cb][kc + 4 + lk][rb]);
                a[g][3] = __float_as_uint(As[cb][kc + 4 + lk][rb + 8]);
            }
#pragma unroll
            for (int n = 0; n < 8; n++) {
                int cc = wn * 64 + n * 8 + lr;
                uint32_t b[2];
                b[0] = tf32_bits(Ws[cb][kc + lk][cc]);
                b[1] = tf32_bits(Ws[cb][kc + 4 + lk][cc]);
#pragma unroll
                for (int g = 0; g < 2; g++) MMA_TF32(d[g][n], a[g], b);
            }
        }
        __syncthreads();
    }
#undef S2_LOAD

    // Store s2[m][bc][l]: d0/d1 adjacent in l -> float2
    const size_t sb = (size_t)m * (BC * LPAD);
#pragma unroll
    for (int g = 0; g < 2; g++) {
#pragma unroll
        for (int n = 0; n < 8; n++) {
            int bc0 = wm * 32 + g * 16 + lr;
            int l   = l0 + wn * 64 + n * 8 + 2 * lk;
            *(float2*)&sht_s2[sb + (size_t)bc0 * LPAD + l] =
                make_float2(d[g][n][0], d[g][n][1]);
            *(float2*)&sht_s2[sb + (size_t)(bc0 + 8) * LPAD + l] =
                make_float2(d[g][n][2], d[g][n][3]);
        }
    }
}

// ---------------------------------------------------------------
__global__ void sht_xpose_out(float* __restrict__ out, unsigned obud) {
    __shared__ float t[32][33];
    const int l0 = blockIdx.x * 32;
    const int m0 = blockIdx.y * 32;
    const int bc = blockIdx.z;

    for (int i = threadIdx.y; i < 32; i += 8) {
        int m = m0 + i;
        float v = 0.f;
        if (m < MMAX)
            v = sht_s2[(size_t)m * (BC * LPAD) + (size_t)bc * LPAD + l0 + threadIdx.x];
        t[i][threadIdx.x] = v;
    }
    __syncthreads();
    for (int i = threadIdx.y; i < 32; i += 8) {
        int l = l0 + i;
        int m = m0 + threadIdx.x;
        if (l < LMAX && m < MMAX) {
            unsigned ci = ((unsigned)bc * LMAX + (unsigned)l) * MMAX + (unsigned)m;
            if (ci < obud) out[ci] = t[threadIdx.x][i];
        }
    }
}

// ---------------------------------------------------------------
extern "C" void kernel_launch(void* const* d_in, const int* in_sizes, int n_in,
                              void* d_out, int out_size) {
    const float* x = nullptr;
    const float* w = nullptr;
    unsigned xbud = 0, wbud = 0;

    for (int i = 0; i < n_in; i++) {
        if (in_sizes[i] == X_ELEMS && !x) { x = (const float*)d_in[i]; xbud = X_ELEMS; }
        else if (in_sizes[i] == W_ELEMS && !w) { w = (const float*)d_in[i]; wbud = W_ELEMS; }
    }
    if (!x && n_in >= 1) {
        x = (const float*)d_in[0];
        long s = in_sizes[0];
        xbud = (unsigned)((s > 0 && s < (long)X_ELEMS) ? s : X_ELEMS);
    }
    if (!w && n_in >= 2) {
        w = (const float*)d_in[1];
        long s = in_sizes[1];
        wbud = (unsigned)((s > 0 && s < (long)W_ELEMS) ? s : W_ELEMS);
    }

    unsigned obud;
    if (out_size <= 0) obud = OUT_REAL;
    else obud = ((unsigned)out_size < (unsigned)OUT_REAL) ? (unsigned)out_size
                                                          : (unsigned)OUT_REAL;

    float* out = (float*)d_out;

    sht_init_trig<<<(K2P * K2P + 255) / 256, 256>>>();
    sht_fold<<<NROWS / 16, 256>>>(x, xbud);
    sht_stage1<<<dim3(361, 4), 256>>>();
    sht_xpose_xfr<<<dim3(12, 4, 361), dim3(32, 8)>>>();
    sht_stage2<<<dim3(3, MMAX), 256>>>(w, wbud);
    sht_xpose_out<<<dim3(12, 12, 128), dim3(32, 8)>>>(out, obud);
}

// round 14
// speedup vs baseline: 2.4623x; 1.1739x over previous
#include <cuda_runtime.h>
#include <math.h>
#include <stdint.h>

// Problem constants
#define NLAT 361
#define NLON 720
#define MMAX 361
#define LMAX 360
#define BC   128
#define NROWS (BC * NLAT)   // 46208

#define X_ELEMS  (BC * NLAT * NLON)
#define W_ELEMS  (MMAX * LMAX * NLAT)
#define OUT_REAL (BC * LMAX * MMAX)

#define K1P 368             // latitude K padded (stage-2)
#define K2P 192             // folded DFT K padded (stage-1)
#define NT1 (K2P / 16)      // 12
#define NT2 (K1P / 16)      // 23
#define LPAD 384
#define SPITCH 132          // stage-1 smem pitch ([k][r] layout)
#define APITCH 20           // stage-2 smem pitch ([row][k] layout)

// -------- static device scratch (zero-initialized at load) --------
__device__ float sht_te[K2P * K2P];
__device__ float sht_to[K2P * K2P];
__device__ float sht_ye[(size_t)K2P * NROWS];
__device__ float sht_yo[(size_t)K2P * NROWS];
__device__ float sht_xfr[(size_t)MMAX * BC * K1P]; // [m][bc][k], tf32-rounded, k-pad zero
__device__ float sht_s2[(size_t)MMAX * BC * LPAD]; // [m][bc][l]

#define CP_ASYNC16(s, g) asm volatile("cp.async.ca.shared.global [%0], [%1], 16;" :: "r"(s), "l"(g) : "memory")
#define CP_ASYNC4(s, g)  asm volatile("cp.async.ca.shared.global [%0], [%1], 4;"  :: "r"(s), "l"(g) : "memory")
#define CP_COMMIT()      asm volatile("cp.async.commit_group;" ::: "memory")
#define CP_WAIT1()       asm volatile("cp.async.wait_group 1;" ::: "memory")
#define CP_WAIT0()       asm volatile("cp.async.wait_group 0;" ::: "memory")

__device__ __forceinline__ float tf32_round(float x) {
    uint32_t u;
    asm("cvt.rna.tf32.f32 %0, %1;" : "=r"(u) : "f"(x));
    return __uint_as_float(u);
}
__device__ __forceinline__ uint32_t tf32_bits(float x) {
    uint32_t u;
    asm("cvt.rna.tf32.f32 %0, %1;" : "=r"(u) : "f"(x));
    return u;
}
#define MMA_TF32(d, a, b) \
    asm volatile("mma.sync.aligned.m16n8k8.row.col.f32.tf32.tf32.f32 " \
        "{%0,%1,%2,%3}, {%4,%5,%6,%7}, {%8,%9}, {%0,%1,%2,%3};" \
        : "+f"((d)[0]), "+f"((d)[1]), "+f"((d)[2]), "+f"((d)[3]) \
        : "r"((a)[0]), "r"((a)[1]), "r"((a)[2]), "r"((a)[3]), "r"((b)[0]), "r"((b)[1]))

// ---------------------------------------------------------------
__global__ void sht_init_trig() {
    int idx = blockIdx.x * blockDim.x + threadIdx.x;
    if (idx >= K2P * K2P) return;
    int k = idx / K2P;
    int j = idx - k * K2P;
    const double scale = 6.283185307179586476925286766559 / (double)NLON;
    float ve = 0.f, vo = 0.f;
    if (k <= 180) {
        if (j <= 180) {
            int r = (k * (2 * j)) % NLON;
            ve = (float)(cos(6.283185307179586476925286766559 * (double)r / (double)NLON) * scale);
        }
        if (j <= 179) {
            int r = (k * (2 * j + 1)) % NLON;
            vo = (float)(cos(6.283185307179586476925286766559 * (double)r / (double)NLON) * scale);
        }
    }
    sht_te[idx] = tf32_round(ve);
    sht_to[idx] = tf32_round(vo);
}

// ---------------------------------------------------------------
__global__ __launch_bounds__(256) void sht_fold(const float* __restrict__ x,
                                                unsigned xbud) {
    __shared__ float xs[16][720];
    const int row0 = blockIdx.x * 16;
    const int tid  = threadIdx.x;

    for (int i = tid; i < 16 * 720; i += 256) {
        int rl = i / 720, n = i - (i / 720) * 720;
        unsigned gi = (unsigned)(row0 + rl) * NLON + (unsigned)n;
        xs[rl][n] = (gi < xbud) ? x[gi] : 0.f;
    }
    __syncthreads();

    const int rl = tid & 15;
#pragma unroll
    for (int it = 0; it < 12; it++) {
        int n = (tid >> 4) + 16 * it;
        float ve = 0.f, vo = 0.f;
        if (n == 0) {
            float a0 = xs[rl][0], a1 = xs[rl][360];
            ve = a0 + a1; vo = a0 - a1;
        } else if (n <= 179) {
            float s1 = xs[rl][n] + xs[rl][720 - n];
            float s2 = xs[rl][360 - n] + xs[rl][360 + n];
            ve = s1 + s2; vo = s1 - s2;
        } else if (n == 180) {
            float s = xs[rl][180] + xs[rl][540];
            ve = s; vo = s;
        }
        size_t o = (size_t)n * NROWS + row0 + rl;
        sht_ye[o] = tf32_round(ve);
        sht_yo[o] = tf32_round(vo);
    }
}

// ---------------------------------------------------------------
// Stage 1 (tensor): 128 r x 128 j per block, K=192, [k][*] smem.
// grid=(361,4): p=by>>1, j0=(by&1)*64.
// Epilogue stores tf32-rounded directly to xfr[m][bc][k].
// ---------------------------------------------------------------
__global__ __launch_bounds__(256, 2) void sht_stage1() {
    __shared__ __align__(16) float As[2][16][SPITCH];
    __shared__ __align__(16) float Bs[2][16][SPITCH];

    const int tid  = threadIdx.x;
    const int row0 = blockIdx.x * 128;
    const int p    = blockIdx.y >> 1;
    const int j0   = (blockIdx.y & 1) * 64;
    const int wid  = tid >> 5;
    const int lane = tid & 31;
    const int wm   = wid & 3;
    const int wn   = wid >> 2;
    const int lr   = lane >> 2;
    const int lk   = lane & 3;

    const float* __restrict__ ya = p ? sht_yo : sht_ye;
    const float* __restrict__ tb = p ? sht_to : sht_te;

    const uint32_t sAs = (uint32_t)__cvta_generic_to_shared(&As[0][0][0]);
    const uint32_t sBs = (uint32_t)__cvta_generic_to_shared(&Bs[0][0][0]);

    float d[2][8][4];
#pragma unroll
    for (int g = 0; g < 2; g++)
#pragma unroll
        for (int n = 0; n < 8; n++)
#pragma unroll
            for (int i = 0; i < 4; i++) d[g][n][i] = 0.f;

#define S1_LOAD(buf, kb) do {                                                  \
        _Pragma("unroll")                                                      \
        for (int i = 0; i < 2; i++) {                                          \
            int f  = tid + i * 256;                                            \
            int kk = f >> 5;                                                   \
            int c4 = (f & 31) * 4;                                             \
            CP_ASYNC16(sAs + (uint32_t)((((buf)*16 + kk)*SPITCH + c4) * 4),    \
                       ya + (size_t)((kb) + kk) * NROWS + row0 + c4);          \
            CP_ASYNC16(sBs + (uint32_t)((((buf)*16 + kk)*SPITCH + c4) * 4),    \
                       tb + ((kb) + kk) * K2P + j0 + c4);                      \
        }                                                                      \
        CP_COMMIT();                                                           \
    } while (0)

    S1_LOAD(0, 0);

    for (int t = 0; t < NT1; t++) {
        if (t + 1 < NT1) { S1_LOAD((t + 1) & 1, 16 * (t + 1)); CP_WAIT1(); }
        else             { CP_WAIT0(); }
        __syncthreads();
        const int cb = t & 1;
#pragma unroll
        for (int kc = 0; kc < 16; kc += 8) {
            uint32_t a[2][4];
#pragma unroll
            for (int g = 0; g < 2; g++) {
                int rb = wm * 32 + g * 16 + lr;
                a[g][0] = __float_as_uint(As[cb][kc + lk][rb]);
                a[g][1] = __float_as_uint(As[cb][kc + lk][rb + 8]);
                a[g][2] = __float_as_uint(As[cb][kc + 4 + lk][rb]);
                a[g][3] = __float_as_uint(As[cb][kc + 4 + lk][rb + 8]);
            }
#pragma unroll
            for (int n = 0; n < 8; n++) {
                int cc = wn * 64 + n * 8 + lr;
                uint32_t b[2];
                b[0] = __float_as_uint(Bs[cb][kc + lk][cc]);
                b[1] = __float_as_uint(Bs[cb][kc + 4 + lk][cc]);
#pragma unroll
                for (int g = 0; g < 2; g++) MMA_TF32(d[g][n], a[g], b);
            }
        }
        __syncthreads();
    }
#undef S1_LOAD

    // Store tf32-rounded xfr[m][bc][k]; m = 2*(j0+jj)+p
#pragma unroll
    for (int g = 0; g < 2; g++) {
#pragma unroll
        for (int n = 0; n < 8; n++) {
#pragma unroll
            for (int e = 0; e < 4; e++) {
                int r  = row0 + wm * 32 + g * 16 + lr + ((e >> 1) << 3);
                int jj = wn * 64 + n * 8 + 2 * lk + (e & 1);
                int m  = 2 * (j0 + jj) + p;
                if (m > 360) continue;
                int bc = r / NLAT;
                int k  = r - bc * NLAT;
                sht_xfr[(size_t)m * BC * K1P + (size_t)bc * K1P + k] =
                    tf32_round(d[g][n][e]);
            }
        }
    }
}

// ---------------------------------------------------------------
// Stage 2 (tensor): s2[m][bc][l] = sum_k xfr[m][bc][k] * w[m][l][k]
// A-tiles [bc][k] pitch-20, 16B cp.async (K1P stride is 16B-aligned).
// W-tiles [l][k] pitch-20, GUARDED 4B cp.async (W row stride 1444B is
// NOT 16B/8B aligned -> scalar only).  128x128, K=368. grid=(3,361).
// ---------------------------------------------------------------
__global__ __launch_bounds__(256, 2) void sht_stage2(const float* __restrict__ w,
                                                     unsigned wbud) {
    __shared__ __align__(16) float As[2][128][APITCH];
    __shared__ __align__(16) float Ws[2][128][APITCH];

    const int tid = threadIdx.x;
    const int m   = blockIdx.y;
    const int l0  = blockIdx.x * 128;
    const int wid  = tid >> 5;
    const int lane = tid & 31;
    const int wm   = wid & 3;
    const int wn   = wid >> 2;
    const int lr   = lane >> 2;
    const int lk   = lane & 3;

    const float* __restrict__ xa = sht_xfr + (size_t)m * BC * K1P;
    const float* __restrict__ wp = w + (size_t)m * (LMAX * NLAT);
    const unsigned wrow_max = (wbud > (unsigned)((size_t)m * (LMAX * NLAT)))
                            ? (unsigned)(wbud - (size_t)m * (LMAX * NLAT)) : 0u;

    const uint32_t sAs = (uint32_t)__cvta_generic_to_shared(&As[0][0][0]);
    const uint32_t sWs = (uint32_t)__cvta_generic_to_shared(&Ws[0][0][0]);

    float d[2][8][4];
#pragma unroll
    for (int g = 0; g < 2; g++)
#pragma unroll
        for (int n = 0; n < 8; n++)
#pragma unroll
            for (int i = 0; i < 4; i++) d[g][n][i] = 0.f;

#define S2_LOAD(buf, kb) do {                                                  \
        _Pragma("unroll")                                                      \
        for (int i = 0; i < 2; i++) {                                          \
            int f   = tid + i * 256;                                           \
            int bcr = f >> 2;                                                  \
            int c4  = (f & 3) * 4;                                             \
            CP_ASYNC16(sAs + (uint32_t)((((buf)*128 + bcr)*APITCH + c4) * 4),  \
                       xa + (size_t)bcr * K1P + (kb) + c4);                    \
        }                                                                      \
        _Pragma("unroll")                                                      \
        for (int i = 0; i < 8; i++) {                                          \
            int f   = tid + i * 256;                                           \
            int lrw = f >> 4;                                                  \
            int kk  = f & 15;                                                  \
            int k   = (kb) + kk;                                               \
            int ll  = l0 + lrw;                                                \
            uint32_t ds = sWs + (uint32_t)((((buf)*128 + lrw)*APITCH + kk) * 4); \
            unsigned ro = (unsigned)ll * NLAT + (unsigned)k;                   \
            if (ll < LMAX && k < NLAT && ro < wrow_max)                        \
                CP_ASYNC4(ds, wp + ro);                                        \
            else                                                               \
                Ws[buf][lrw][kk] = 0.f;                                        \
        }                                                                      \
        CP_COMMIT();                                                           \
    } while (0)

    S2_LOAD(0, 0);

    for (int t = 0; t < NT2; t++) {
        if (t + 1 < NT2) { S2_LOAD((t + 1) & 1, 16 * (t + 1)); CP_WAIT1(); }
        else             { CP_WAIT0(); }
        __syncthreads();
        const int cb = t & 1;
#pragma unroll
        for (int kc = 0; kc < 16; kc += 8) {
            uint32_t a[2][4];
#pragma unroll
            for (int g = 0; g < 2; g++) {
                int rb = wm * 32 + g * 16 + lr;
                a[g][0] = __float_as_uint(As[cb][rb][kc + lk]);
                a[g][1] = __float_as_uint(As[cb][rb + 8][kc + lk]);
                a[g][2] = __float_as_uint(As[cb][rb][kc + 4 + lk]);
                a[g][3] = __float_as_uint(As[cb][rb + 8][kc + 4 + lk]);
            }
#pragma unroll
            for (int n = 0; n < 8; n++) {
                int cc = wn * 64 + n * 8 + lr;
                uint32_t b[2];
                b[0] = tf32_bits(Ws[cb][cc][kc + lk]);
                b[1] = tf32_bits(Ws[cb][cc][kc + 4 + lk]);
#pragma unroll
                for (int g = 0; g < 2; g++) MMA_TF32(d[g][n], a[g], b);
            }
        }
        __syncthreads();
    }
#undef S2_LOAD

    // Coalesced float2 store to s2[m][bc][l]
    const size_t sb = (size_t)m * (BC * LPAD);
#pragma unroll
    for (int g = 0; g < 2; g++) {
#pragma unroll
        for (int n = 0; n < 8; n++) {
            int bc0 = wm * 32 + g * 16 + lr;
            int l   = l0 + wn * 64 + n * 8 + 2 * lk;
            *(float2*)&sht_s2[sb + (size_t)bc0 * LPAD + l] =
                make_float2(d[g][n][0], d[g][n][1]);
            *(float2*)&sht_s2[sb + (size_t)(bc0 + 8) * LPAD + l] =
                make_float2(d[g][n][2], d[g][n][3]);
        }
    }
}

// ---------------------------------------------------------------
// Output transpose: s2[m][bc][l] -> out[(bc*360+l)*361+m]
// 4 bc per block.  grid=(12 lt, 12 mt, 32), block=(32,8)
// ---------------------------------------------------------------
__global__ void sht_xpose_out(float* __restrict__ out, unsigned obud) {
    __shared__ float t[32][33];
    const int l0 = blockIdx.x * 32;
    const int m0 = blockIdx.y * 32;

    for (int bz = 0; bz < 4; bz++) {
        const int bc = blockIdx.z * 4 + bz;
        for (int i = threadIdx.y; i < 32; i += 8) {
            int m = m0 + i;
            float v = 0.f;
            if (m < MMAX)
                v = sht_s2[(size_t)m * (BC * LPAD) + (size_t)bc * LPAD + l0 + threadIdx.x];
            t[i][threadIdx.x] = v;
        }
        __syncthreads();
        for (int i = threadIdx.y; i < 32; i += 8) {
            int l = l0 + i;
            int m = m0 + threadIdx.x;
            if (l < LMAX && m < MMAX) {
                unsigned ci = ((unsigned)bc * LMAX + (unsigned)l) * MMAX + (unsigned)m;
                if (ci < obud) out[ci] = t[threadIdx.x][i];
            }
        }
        __syncthreads();
    }
}

// ---------------------------------------------------------------
extern "C" void kernel_launch(void* const* d_in, const int* in_sizes, int n_in,
                              void* d_out, int out_size) {
    const float* x = nullptr;
    const float* w = nullptr;
    unsigned xbud = 0, wbud = 0;

    for (int i = 0; i < n_in; i++) {
        if (in_sizes[i] == X_ELEMS && !x) { x = (const float*)d_in[i]; xbud = X_ELEMS; }
        else if (in_sizes[i] == W_ELEMS && !w) { w = (const float*)d_in[i]; wbud = W_ELEMS; }
    }
    if (!x && n_in >= 1) {
        x = (const float*)d_in[0];
        long s = in_sizes[0];
        xbud = (unsigned)((s > 0 && s < (long)X_ELEMS) ? s : X_ELEMS);
    }
    if (!w && n_in >= 2) {
        w = (const float*)d_in[1];
        long s = in_sizes[1];
        wbud = (unsigned)((s > 0 && s < (long)W_ELEMS) ? s : W_ELEMS);
    }

    unsigned obud;
    if (out_size <= 0) obud = OUT_REAL;
    else obud = ((unsigned)out_size < (unsigned)OUT_REAL) ? (unsigned)out_size
                                                          : (unsigned)OUT_REAL;

    float* out = (float*)d_out;

    sht_init_trig<<<(K2P * K2P + 255) / 256, 256>>>();
    sht_fold<<<NROWS / 16, 256>>>(x, xbud);
    sht_stage1<<<dim3(361, 4), 256>>>();
    sht_stage2<<<dim3(3, MMAX), 256>>>(w, wbud);
    sht_xpose_out<<<dim3(12, 12, 32), dim3(32, 8)>>>(out, obud);
}